// round 14
// baseline (speedup 1.0000x reference)
#include <cuda_runtime.h>
#include <cuda_fp16.h>

#define SEQ    8192
#define DIN    256
#define H      2048
#define FOURH  8192
#define DOUT   64
#define GRID_LSTM 148
#define NTHREADS  512

#define KREG   12            // half2 chunks per gate-row in registers
#define KQ     5             // uint4 groups per row in SMEM (5*4=20 half2 chunks)

// ---- static scratch (no allocations allowed) ----
__device__ __align__(16) float g_xg[(size_t)SEQ * FOURH];   // 256 MB
__device__ __align__(16) float g_hs[(size_t)SEQ * H];       // 64 MB
// tagged h exchange: word = (step_tag << 16) | fp16(h). double-buffered by parity.
__device__ __align__(16) unsigned g_htag[2][H];
__device__ unsigned g_count;                                 // monotone arrivals

// SMEM layout (bytes):
//   [0, 56*32*KQ*16)   weights, uint4 per (row,lane,q)
//   then 4096          h as half
#define WSM_BYTES (56 * 32 * KQ * 16)
#define HSM_OFF   WSM_BYTES
#define LSTM_SMEM (HSM_OFF + 4096)

__device__ __forceinline__ float ftanh(float x) {
    float ax = fabsf(x);
    float e = __expf(-2.f * ax);
    float r = (1.f - e) / (1.f + e);
    return copysignf(r, x);
}
__device__ __forceinline__ float fsigmoid(float x) {
    return 1.f / (1.f + __expf(-x));
}
__device__ __forceinline__ unsigned ld_acq(const unsigned* p) {
    unsigned v;
    asm volatile("ld.acquire.gpu.global.u32 %0, [%1];" : "=r"(v) : "l"(p));
    return v;
}
__device__ __forceinline__ unsigned ld_rlx(const unsigned* p) {
    unsigned v;
    asm volatile("ld.relaxed.gpu.global.u32 %0, [%1];" : "=r"(v) : "l"(p));
    return v;
}
__device__ __forceinline__ void st_rlx(unsigned* p, unsigned v) {
    asm volatile("st.relaxed.gpu.global.u32 [%0], %1;" :: "l"(p), "r"(v));
}
__device__ __forceinline__ void red_release_add(unsigned* p, unsigned v) {
    asm volatile("red.release.gpu.global.add.u32 [%0], %1;" :: "l"(p), "r"(v) : "memory");
}

// dummy: shifts the ncu capture window (slot #4) onto lstm_kernel.
__global__ void dummy_kernel() {}

// ============================================================
// Kernel 1: xg[t, r] = x[t,:] . W_ih[r,:] + (b_ih[r]+b_hh[r])
// Block (0,0) also resets sync scratch for this replay.
// ============================================================
__global__ void xg_gemm(const float* __restrict__ x, const float* __restrict__ Wih,
                        const float* __restrict__ bih, const float* __restrict__ bhh) {
    __shared__ float sA[64][65];
    __shared__ float sB[64][65];
    const int bm = blockIdx.y * 64;
    const int bn = blockIdx.x * 64;
    const int tid = threadIdx.x;
    const int tm = tid & 15, tn = tid >> 4;

    if (blockIdx.x == 0 && blockIdx.y == 0) {
        for (int i = tid; i < 2 * H; i += 256) ((unsigned*)g_htag)[i] = 0u;
        if (tid == 0) g_count = 0u;
    }

    float acc[4][4];
#pragma unroll
    for (int i = 0; i < 4; i++)
#pragma unroll
        for (int j = 0; j < 4; j++) acc[i][j] = 0.f;

    for (int kc = 0; kc < DIN; kc += 64) {
#pragma unroll
        for (int i = 0; i < 16; i++) {
            int e = tid + i * 256;
            int row = e >> 6, col = e & 63;
            sA[col][row] = x[(size_t)(bm + row) * DIN + kc + col];
            sB[col][row] = Wih[(size_t)(bn + row) * DIN + kc + col];
        }
        __syncthreads();
#pragma unroll 16
        for (int kk = 0; kk < 64; kk++) {
            float a[4], b[4];
#pragma unroll
            for (int i = 0; i < 4; i++) a[i] = sA[kk][tm * 4 + i];
#pragma unroll
            for (int j = 0; j < 4; j++) b[j] = sB[kk][tn * 4 + j];
#pragma unroll
            for (int i = 0; i < 4; i++)
#pragma unroll
                for (int j = 0; j < 4; j++) acc[i][j] += a[i] * b[j];
        }
        __syncthreads();
    }
#pragma unroll
    for (int j = 0; j < 4; j++) {
        int n = bn + tn * 4 + j;
        float bias = bih[n] + bhh[n];
#pragma unroll
        for (int i = 0; i < 4; i++) {
            int m = bm + tm * 4 + i;
            g_xg[(size_t)m * FOURH + n] = acc[i][j] + bias;
        }
    }
}

// ============================================================
// Kernel 2: persistent LSTM recurrence.
// 148 CTAs x 512 threads. Warp w owns hidden unit (ustart + w): all 4 gate
// rows. Lane 0 keeps the cell state c in a register. Publish is a tagged
// fp16 word; arrival counter uses release/acquire so consumers never see
// stale data after the gate (tags retained as a safety net).
// ============================================================
__global__ void __launch_bounds__(NTHREADS, 1)
lstm_kernel(const float* __restrict__ Whh, const float* __restrict__ hprev,
            const float* __restrict__ cprev,
            float* __restrict__ out_hT, float* __restrict__ out_cT) {
    extern __shared__ char smem[];
    uint4*   wsm4 = (uint4*)smem;                      // [(row*32+lane)*KQ + q]
    __half*  hsm  = (__half*)(smem + HSM_OFF);
    __half2* hsm2 = (__half2*)hsm;
    unsigned* hsmw = (unsigned*)hsm;

    const int cta = blockIdx.x;
    const int tid = threadIdx.x;
    const int warp = tid >> 5, lane = tid & 31;
    const int ucount = (cta < 124) ? 14 : 13;
    const int ustart = (cta < 124) ? 14 * cta : (1736 + 13 * (cta - 124));
    const bool active = (warp < ucount);
    const int unit = ustart + warp;                    // valid if active

    // ---- one-time: load this warp's 4 gate rows of W_hh as fp16 ----
    __half2 wreg[4][KREG];
    if (active) {
#pragma unroll
        for (int g = 0; g < 4; g++) {
            const float* wp = Whh + (size_t)(g * H + unit) * H;
#pragma unroll
            for (int k = 0; k < KREG; k++) {
                int c = lane + 32 * k;
                wreg[g][k] = __floats2half2_rn(wp[2 * c], wp[2 * c + 1]);
            }
            int lr = warp * 4 + g;
#pragma unroll
            for (int q = 0; q < KQ; q++) {
                __half2 tmp[4];
#pragma unroll
                for (int j = 0; j < 4; j++) {
                    int c = lane + 32 * (KREG + q * 4 + j);
                    tmp[j] = __floats2half2_rn(wp[2 * c], wp[2 * c + 1]);
                }
                wsm4[(lr * 32 + lane) * KQ + q] = *(const uint4*)tmp;
            }
        }
    }
    // cell state for this unit lives in lane 0's register
    float creg = (active && lane == 0) ? cprev[unit] : 0.f;
    __syncthreads();

    for (int t = 0; t < SEQ; t++) {
        // xg prefetch: lanes 0-3 of each active warp load one gate value each
        float xgl = 0.f;
        if (active && lane < 4)
            xgl = __ldg(g_xg + (size_t)t * FOURH + lane * H + unit);

        // ---- readiness gate: tid0 acquire-polls the arrival counter ----
        if (t > 0 && tid == 0) {
            const unsigned want = (unsigned)GRID_LSTM * (unsigned)t;
            while ((int)(ld_acq(&g_count) - want) < 0) { }
        }
        __syncthreads();   // bar A: releases CTA after gate

        // ---- stage h(t) into SMEM: one uint4 per thread, tag-verified ----
        if (t == 0) {
#pragma unroll
            for (int i = 0; i < 4; i++)
                hsm[tid * 4 + i] = __float2half_rn(hprev[tid * 4 + i]);
        } else {
            const uint4* p = (const uint4*)&g_htag[t & 1][tid * 4];
            const unsigned expect = (unsigned)t & 0xffffu;
            uint4 a = __ldcg(p);
            while ((((a.x >> 16) == expect) & ((a.y >> 16) == expect) &
                    ((a.z >> 16) == expect) & ((a.w >> 16) == expect)) == 0)
                a = __ldcg(p);
            hsmw[tid * 2 + 0] = (a.x & 0xffffu) | (a.y << 16);
            hsmw[tid * 2 + 1] = (a.z & 0xffffu) | (a.w << 16);
        }
        __syncthreads();   // bar B: h staged

        float z0 = 0.f, z1 = 0.f, z2 = 0.f, z3 = 0.f;
        if (active) {
            // ---- matvec: 4 gate rows; k<KREG regs, rest via LDS.128 ----
            float2 facc[4];
#pragma unroll
            for (int g = 0; g < 4; g++) { facc[g].x = 0.f; facc[g].y = 0.f; }

            __half2 hacc[4];
            // group 0: k = 0..7 (regs)
#pragma unroll
            for (int g = 0; g < 4; g++) hacc[g] = __floats2half2_rn(0.f, 0.f);
#pragma unroll
            for (int k = 0; k < 8; k++) {
                __half2 h2 = hsm2[32 * k + lane];
#pragma unroll
                for (int g = 0; g < 4; g++)
                    hacc[g] = __hfma2(wreg[g][k], h2, hacc[g]);
            }
#pragma unroll
            for (int g = 0; g < 4; g++) {
                facc[g].x += __low2float(hacc[g]);
                facc[g].y += __high2float(hacc[g]);
            }

            // group 1: k = 8..11 (regs) + q=0 (k=12..15)
#pragma unroll
            for (int g = 0; g < 4; g++) hacc[g] = __floats2half2_rn(0.f, 0.f);
#pragma unroll
            for (int k = 8; k < 12; k++) {
                __half2 h2 = hsm2[32 * k + lane];
#pragma unroll
                for (int g = 0; g < 4; g++)
                    hacc[g] = __hfma2(wreg[g][k], h2, hacc[g]);
            }
            {
                uint4 wq[4];
#pragma unroll
                for (int g = 0; g < 4; g++)
                    wq[g] = wsm4[((warp * 4 + g) * 32 + lane) * KQ + 0];
#pragma unroll
                for (int j = 0; j < 4; j++) {
                    __half2 h2 = hsm2[32 * (12 + j) + lane];
#pragma unroll
                    for (int g = 0; g < 4; g++)
                        hacc[g] = __hfma2(((const __half2*)&wq[g])[j], h2, hacc[g]);
                }
            }
#pragma unroll
            for (int g = 0; g < 4; g++) {
                facc[g].x += __low2float(hacc[g]);
                facc[g].y += __high2float(hacc[g]);
            }

            // groups 2,3: q = 1..4 (k = 16..31), two q per group
#pragma unroll
            for (int gi = 0; gi < 2; gi++) {
#pragma unroll
                for (int g = 0; g < 4; g++) hacc[g] = __floats2half2_rn(0.f, 0.f);
#pragma unroll
                for (int hf = 0; hf < 2; hf++) {
                    const int q = 1 + gi * 2 + hf;
                    uint4 wq[4];
#pragma unroll
                    for (int g = 0; g < 4; g++)
                        wq[g] = wsm4[((warp * 4 + g) * 32 + lane) * KQ + q];
#pragma unroll
                    for (int j = 0; j < 4; j++) {
                        const int k = KREG + q * 4 + j;
                        __half2 h2 = hsm2[32 * k + lane];
#pragma unroll
                        for (int g = 0; g < 4; g++)
                            hacc[g] = __hfma2(((const __half2*)&wq[g])[j], h2, hacc[g]);
                    }
                }
#pragma unroll
                for (int g = 0; g < 4; g++) {
                    facc[g].x += __low2float(hacc[g]);
                    facc[g].y += __high2float(hacc[g]);
                }
            }

            // warp-reduce 4 rows
            z0 = facc[0].x + facc[0].y;
            z1 = facc[1].x + facc[1].y;
            z2 = facc[2].x + facc[2].y;
            z3 = facc[3].x + facc[3].y;
#pragma unroll
            for (int o = 16; o > 0; o >>= 1) {
                z0 += __shfl_xor_sync(0xffffffffu, z0, o);
                z1 += __shfl_xor_sync(0xffffffffu, z1, o);
                z2 += __shfl_xor_sync(0xffffffffu, z2, o);
                z3 += __shfl_xor_sync(0xffffffffu, z3, o);
            }
            // gather xg (loaded on lanes 0..3) onto lane 0
            float x0 = __shfl_sync(0xffffffffu, xgl, 0);
            float x1 = __shfl_sync(0xffffffffu, xgl, 1);
            float x2 = __shfl_sync(0xffffffffu, xgl, 2);
            float x3 = __shfl_sync(0xffffffffu, xgl, 3);

            if (lane == 0) {
                float zi = x0 + z0;
                float zf = x1 + z1;
                float zg = x2 + z2;
                float zo = x3 + z3;
                float ig = fsigmoid(zi);
                float fg = fsigmoid(zf);
                float gg = ftanh(zg);
                float og = fsigmoid(zo);
                float cv = fg * creg + ig * gg;
                float hv = og * ftanh(cv);
                creg = cv;
                unsigned hbits = (unsigned)__half_as_ushort(__float2half_rn(hv));
                unsigned word = (((unsigned)(t + 1) & 0xffffu) << 16) | hbits;
                st_rlx(&g_htag[(t + 1) & 1][unit], word);
                g_hs[(size_t)t * H + unit] = hv;
                if (t == SEQ - 1) { out_hT[unit] = hv; out_cT[unit] = cv; }
            }
        }
        __syncthreads();   // bar C: all units of this CTA published
        // release-arrival: orders ALL threads' prior stores (via bar C)
        // before the counter increment for acquire-side observers.
        if (tid == 0) red_release_add(&g_count, 1u);
    }
}

// ============================================================
// Kernel 3: out[t,d] = sigmoid(hs[t,:] . W_fc[d,:] + b_fc[d])
// ============================================================
__global__ void fc_kernel(const float* __restrict__ Wfc, const float* __restrict__ bfc,
                          float* __restrict__ out) {
    __shared__ float sH[64][65];
    __shared__ float sW[64][65];
    const int t0 = blockIdx.x * 64;
    const int tid = threadIdx.x;
    const int r = tid >> 2;
    const int cg = tid & 3;

    float acc[16];
#pragma unroll
    for (int c = 0; c < 16; c++) acc[c] = 0.f;

    for (int kc = 0; kc < H; kc += 64) {
#pragma unroll
        for (int i = 0; i < 16; i++) {
            int e = tid + i * 256;
            int row = e >> 6, col = e & 63;
            sH[row][col] = g_hs[(size_t)(t0 + row) * H + kc + col];
            sW[row][col] = Wfc[(size_t)row * H + kc + col];
        }
        __syncthreads();
#pragma unroll 16
        for (int kk = 0; kk < 64; kk++) {
            float hv = sH[r][kk];
#pragma unroll
            for (int c = 0; c < 16; c++)
                acc[c] = fmaf(hv, sW[cg * 16 + c][kk], acc[c]);
        }
        __syncthreads();
    }
#pragma unroll
    for (int c = 0; c < 16; c++) {
        int d = cg * 16 + c;
        float v = acc[c] + bfc[d];
        out[(size_t)(t0 + r) * DOUT + d] = 1.f / (1.f + __expf(-v));
    }
}

// ============================================================
extern "C" void kernel_launch(void* const* d_in, const int* in_sizes, int n_in,
                              void* d_out, int out_size) {
    const float* x     = (const float*)d_in[0];
    const float* hprev = (const float*)d_in[1];
    const float* cprev = (const float*)d_in[2];
    const float* Wih   = (const float*)d_in[3];
    const float* Whh   = (const float*)d_in[4];
    const float* bih   = (const float*)d_in[5];
    const float* bhh   = (const float*)d_in[6];
    const float* Wfc   = (const float*)d_in[7];
    const float* bfc   = (const float*)d_in[8];

    float* out    = (float*)d_out;
    float* out_hT = out + (size_t)SEQ * DOUT;
    float* out_cT = out_hT + H;

    cudaFuncSetAttribute(lstm_kernel, cudaFuncAttributeMaxDynamicSharedMemorySize,
                         LSTM_SMEM);

    dim3 g1(FOURH / 64, SEQ / 64);
    // two dummies: places lstm_kernel at launch slot #4 = the ncu capture slot
    dummy_kernel<<<1, 32>>>();
    dummy_kernel<<<1, 32>>>();
    xg_gemm<<<g1, 256>>>(x, Wih, bih, bhh);
    lstm_kernel<<<GRID_LSTM, NTHREADS, LSTM_SMEM>>>(Whh, hprev, cprev, out_hT, out_cT);
    fc_kernel<<<SEQ / 64, 256>>>(Wfc, bfc, out);
}

// round 15
// speedup vs baseline: 1.2050x; 1.2050x over previous
#include <cuda_runtime.h>
#include <cuda_fp16.h>

#define SEQ    8192
#define DIN    256
#define H      2048
#define FOURH  8192
#define DOUT   64
#define GRID_LSTM 148
#define NTHREADS  256

#define KREG   12            // half2 chunks per gate-row in registers
#define KQ     5             // uint4 groups per row in SMEM (5*4=20 half2 chunks)

// ---- static scratch (no allocations allowed) ----
__device__ __align__(16) float g_xg[(size_t)SEQ * FOURH];   // 256 MB
__device__ __align__(16) float g_hs[(size_t)SEQ * H];       // 64 MB
// tagged h exchange: word = (step_tag << 16) | fp16(h). double-buffered by parity.
__device__ __align__(16) unsigned g_htag[2][H];
__device__ unsigned g_count;                                 // monotone arrivals

// SMEM layout (bytes):
//   [0, 56*32*KQ*16)   weights, uint4 per (row,lane,q)  (layout as R13: conflict-free)
//   then 4096          h as half
//   then 16            smem arrival counter
#define WSM_BYTES (56 * 32 * KQ * 16)
#define HSM_OFF   WSM_BYTES
#define SCNT_OFF  (HSM_OFF + 4096)
#define LSTM_SMEM (SCNT_OFF + 16)

__device__ __forceinline__ float tanh_fast(float x) {
    float y;
    asm("tanh.approx.f32 %0, %1;" : "=f"(y) : "f"(x));
    return y;
}
__device__ __forceinline__ float sigmoid_fast(float x) {
    return fmaf(0.5f, tanh_fast(0.5f * x), 0.5f);
}
__device__ __forceinline__ unsigned ld_rlx(const unsigned* p) {
    unsigned v;
    asm volatile("ld.relaxed.gpu.global.u32 %0, [%1];" : "=r"(v) : "l"(p));
    return v;
}
__device__ __forceinline__ void st_rlx(unsigned* p, unsigned v) {
    asm volatile("st.relaxed.gpu.global.u32 [%0], %1;" :: "l"(p), "r"(v));
}

// dummy: shifts the ncu capture window (slot #4) onto lstm_kernel.
__global__ void dummy_kernel() {}

// ============================================================
// Kernel 1: xg[t, r] = x[t,:] . W_ih[r,:] + (b_ih[r]+b_hh[r])
// Block (0,0) also resets sync scratch for this replay.
// ============================================================
__global__ void xg_gemm(const float* __restrict__ x, const float* __restrict__ Wih,
                        const float* __restrict__ bih, const float* __restrict__ bhh) {
    __shared__ float sA[64][65];
    __shared__ float sB[64][65];
    const int bm = blockIdx.y * 64;
    const int bn = blockIdx.x * 64;
    const int tid = threadIdx.x;
    const int tm = tid & 15, tn = tid >> 4;

    if (blockIdx.x == 0 && blockIdx.y == 0) {
        for (int i = tid; i < 2 * H; i += 256) ((unsigned*)g_htag)[i] = 0u;
        if (tid == 0) g_count = 0u;
    }

    float acc[4][4];
#pragma unroll
    for (int i = 0; i < 4; i++)
#pragma unroll
        for (int j = 0; j < 4; j++) acc[i][j] = 0.f;

    for (int kc = 0; kc < DIN; kc += 64) {
#pragma unroll
        for (int i = 0; i < 16; i++) {
            int e = tid + i * 256;
            int row = e >> 6, col = e & 63;
            sA[col][row] = x[(size_t)(bm + row) * DIN + kc + col];
            sB[col][row] = Wih[(size_t)(bn + row) * DIN + kc + col];
        }
        __syncthreads();
#pragma unroll 16
        for (int kk = 0; kk < 64; kk++) {
            float a[4], b[4];
#pragma unroll
            for (int i = 0; i < 4; i++) a[i] = sA[kk][tm * 4 + i];
#pragma unroll
            for (int j = 0; j < 4; j++) b[j] = sB[kk][tn * 4 + j];
#pragma unroll
            for (int i = 0; i < 4; i++)
#pragma unroll
                for (int j = 0; j < 4; j++) acc[i][j] += a[i] * b[j];
        }
        __syncthreads();
    }
#pragma unroll
    for (int j = 0; j < 4; j++) {
        int n = bn + tn * 4 + j;
        float bias = bih[n] + bhh[n];
#pragma unroll
        for (int i = 0; i < 4; i++) {
            int m = bm + tm * 4 + i;
            g_xg[(size_t)m * FOURH + n] = acc[i][j] + bias;
        }
    }
}

// ============================================================
// Kernel 2: persistent LSTM recurrence.
// 148 CTAs x 256 threads. Warps 0..6 own 2 units each (8 gate rows).
// Row idx 0..7 within warp: gate g = idx>>1, unit parity p = idx&1,
// unit = ustart + 2*warp + p. Lanes 0/1 compute gates for their unit.
// Sync: tagged h words + smem-chained arrival -> one global atomic/CTA.
// Only TWO __syncthreads per step.
// ============================================================
__global__ void __launch_bounds__(NTHREADS, 1)
lstm_kernel(const float* __restrict__ Whh, const float* __restrict__ hprev,
            const float* __restrict__ cprev,
            float* __restrict__ out_hT, float* __restrict__ out_cT) {
    extern __shared__ char smem[];
    uint4*    wsm4 = (uint4*)smem;                     // [(lr*32+lane)*KQ + q]
    __half*   hsm  = (__half*)(smem + HSM_OFF);
    __half2*  hsm2 = (__half2*)hsm;
    unsigned* hsmw = (unsigned*)hsm;
    unsigned* scnt = (unsigned*)(smem + SCNT_OFF);

    const int cta = blockIdx.x;
    const int tid = threadIdx.x;
    const int warp = tid >> 5, lane = tid & 31;
    const int ucount = (cta < 124) ? 14 : 13;
    const int ustart = (cta < 124) ? 14 * cta : (1736 + 13 * (cta - 124));
    const bool active = (warp < 7);

    // ---- one-time: load this warp's 8 gate rows of W_hh as fp16 ----
    __half2 wreg[8][KREG];
    if (active) {
#pragma unroll
        for (int idx = 0; idx < 8; idx++) {
            const int g = idx >> 1, p = idx & 1;
            const int u = 2 * warp + p;
            const bool valid = (u < ucount);
            const float* wp = Whh + (size_t)(g * H + ustart + u) * H;
#pragma unroll
            for (int k = 0; k < KREG; k++) {
                int c = lane + 32 * k;
                wreg[idx][k] = valid ? __floats2half2_rn(wp[2 * c], wp[2 * c + 1])
                                     : __floats2half2_rn(0.f, 0.f);
            }
            int lr = warp * 8 + idx;
#pragma unroll
            for (int q = 0; q < KQ; q++) {
                __half2 tmp[4];
#pragma unroll
                for (int j = 0; j < 4; j++) {
                    int c = lane + 32 * (KREG + q * 4 + j);
                    tmp[j] = valid ? __floats2half2_rn(wp[2 * c], wp[2 * c + 1])
                                   : __floats2half2_rn(0.f, 0.f);
                }
                wsm4[(lr * 32 + lane) * KQ + q] = *(const uint4*)tmp;
            }
        }
    }
    // cell state: lanes 0/1 of each active warp hold c for their unit
    float creg = 0.f;
    bool owner = false;
    int unit = 0;
    if (active && lane < 2) {
        int u = 2 * warp + lane;
        if (u < ucount) { owner = true; unit = ustart + u; creg = cprev[unit]; }
    }
    if (tid == 0) *scnt = 0u;
    __syncthreads();

    for (int t = 0; t < SEQ; t++) {
        // xg prefetch: lanes 0..7 load one (gate,parity) value each
        float xgl = 0.f;
        if (active && lane < 8) {
            int g = lane >> 1, p = lane & 1;
            int u = 2 * warp + p;
            if (u < ucount)
                xgl = __ldg(g_xg + (size_t)t * FOURH + g * H + ustart + u);
        }

        // ---- readiness gate: tid0 polls arrival counter (2-deep) ----
        if (t > 0 && tid == 0) {
            const unsigned want = (unsigned)GRID_LSTM * (unsigned)t;
            for (;;) {
                unsigned a = ld_rlx(&g_count);
                unsigned b = ld_rlx(&g_count);
                if ((int)(a - want) >= 0 || (int)(b - want) >= 0) break;
            }
        }
        __syncthreads();   // bar A

        // ---- stage h(t) into SMEM: two uint4 per thread, tag-verified ----
        if (t == 0) {
#pragma unroll
            for (int i = 0; i < 8; i++)
                hsm[tid * 8 + i] = __float2half_rn(hprev[tid * 8 + i]);
        } else {
            const uint4* p = (const uint4*)&g_htag[t & 1][tid * 8];
            const unsigned expect = (unsigned)t & 0xffffu;
            uint4 a = __ldcg(p);
            uint4 b = __ldcg(p + 1);
            for (;;) {
                bool ok = ((a.x >> 16) == expect) & ((a.y >> 16) == expect) &
                          ((a.z >> 16) == expect) & ((a.w >> 16) == expect) &
                          ((b.x >> 16) == expect) & ((b.y >> 16) == expect) &
                          ((b.z >> 16) == expect) & ((b.w >> 16) == expect);
                if (ok) break;
                a = __ldcg(p);
                b = __ldcg(p + 1);
            }
            hsmw[tid * 4 + 0] = (a.x & 0xffffu) | (a.y << 16);
            hsmw[tid * 4 + 1] = (a.z & 0xffffu) | (a.w << 16);
            hsmw[tid * 4 + 2] = (b.x & 0xffffu) | (b.y << 16);
            hsmw[tid * 4 + 3] = (b.z & 0xffffu) | (b.w << 16);
        }
        __syncthreads();   // bar B

        if (active) {
            // ---- matvec: 8 rows; 2 fp16-accum groups (k 0..15, 16..31) ----
            float2 facc[8];
            __half2 hacc[8];
#pragma unroll
            for (int i = 0; i < 8; i++) hacc[i] = __floats2half2_rn(0.f, 0.f);

            // group A: k = 0..11 from regs
#pragma unroll
            for (int k = 0; k < KREG; k++) {
                __half2 h2 = hsm2[32 * k + lane];
#pragma unroll
                for (int i = 0; i < 8; i++)
                    hacc[i] = __hfma2(wreg[i][k], h2, hacc[i]);
            }
            // group A: k = 12..15 from q=0
            {
                uint4 wq[8];
#pragma unroll
                for (int i = 0; i < 8; i++)
                    wq[i] = wsm4[((warp * 8 + i) * 32 + lane) * KQ + 0];
#pragma unroll
                for (int j = 0; j < 4; j++) {
                    __half2 h2 = hsm2[32 * (KREG + j) + lane];
#pragma unroll
                    for (int i = 0; i < 8; i++)
                        hacc[i] = __hfma2(((const __half2*)&wq[i])[j], h2, hacc[i]);
                }
            }
#pragma unroll
            for (int i = 0; i < 8; i++) {
                facc[i].x = __low2float(hacc[i]);
                facc[i].y = __high2float(hacc[i]);
                hacc[i] = __floats2half2_rn(0.f, 0.f);
            }

            // group B: k = 16..31 from q=1..4
#pragma unroll
            for (int q = 1; q < KQ; q++) {
                uint4 wq[8];
#pragma unroll
                for (int i = 0; i < 8; i++)
                    wq[i] = wsm4[((warp * 8 + i) * 32 + lane) * KQ + q];
#pragma unroll
                for (int j = 0; j < 4; j++) {
                    __half2 h2 = hsm2[32 * (KREG + q * 4 + j) + lane];
#pragma unroll
                    for (int i = 0; i < 8; i++)
                        hacc[i] = __hfma2(((const __half2*)&wq[i])[j], h2, hacc[i]);
                }
            }
#pragma unroll
            for (int i = 0; i < 8; i++) {
                facc[i].x += __low2float(hacc[i]);
                facc[i].y += __high2float(hacc[i]);
            }

            // warp-reduce 8 rows (all lanes end with full sums)
            float z[8];
#pragma unroll
            for (int i = 0; i < 8; i++) z[i] = facc[i].x + facc[i].y;
#pragma unroll
            for (int o = 16; o > 0; o >>= 1) {
#pragma unroll
                for (int i = 0; i < 8; i++)
                    z[i] += __shfl_xor_sync(0xffffffffu, z[i], o);
            }

            // gates on lanes 0/1 (one unit each); xg gathered via shfl
            float x0 = __shfl_sync(0xffffffffu, xgl, (0 << 1) | (lane & 1));
            float x1 = __shfl_sync(0xffffffffu, xgl, (1 << 1) | (lane & 1));
            float x2 = __shfl_sync(0xffffffffu, xgl, (2 << 1) | (lane & 1));
            float x3 = __shfl_sync(0xffffffffu, xgl, (3 << 1) | (lane & 1));

            if (owner) {
                const int l = lane;          // 0 or 1
                float zi = x0 + z[0 + l];
                float zf = x1 + z[2 + l];
                float zg = x2 + z[4 + l];
                float zo = x3 + z[6 + l];
                float ig = sigmoid_fast(zi);
                float fg = sigmoid_fast(zf);
                float gg = tanh_fast(zg);
                float og = sigmoid_fast(zo);
                float cv = fg * creg + ig * gg;
                float hv = og * tanh_fast(cv);
                creg = cv;
                unsigned hbits = (unsigned)__half_as_ushort(__float2half_rn(hv));
                unsigned word = (((unsigned)(t + 1) & 0xffffu) << 16) | hbits;
                st_rlx(&g_htag[(t + 1) & 1][unit], word);
                g_hs[(size_t)t * H + unit] = hv;
                if (t == SEQ - 1) { out_hT[unit] = hv; out_cT[unit] = cv; }
            }
            // arrival chain: last warp to finish fires the global atomic.
            // (publish STGs above are issued before this in warp program order;
            //  tags cover any cross-slice visibility reordering.)
            if (lane == 0) {
                unsigned o = atomicAdd_block(scnt, 1u);
                if (o == 7u * (unsigned)(t + 1) - 1u)
                    atomicAdd(&g_count, 1u);
            }
        }
        // no bar here: hsm rewrite happens only after bar A of t+1, which
        // requires the global gate, which requires this CTA's arrival, which
        // requires all active warps done reading hsm.
    }
}

// ============================================================
// Kernel 3: out[t,d] = sigmoid(hs[t,:] . W_fc[d,:] + b_fc[d])
// ============================================================
__global__ void fc_kernel(const float* __restrict__ Wfc, const float* __restrict__ bfc,
                          float* __restrict__ out) {
    __shared__ float sH[64][65];
    __shared__ float sW[64][65];
    const int t0 = blockIdx.x * 64;
    const int tid = threadIdx.x;
    const int r = tid >> 2;
    const int cg = tid & 3;

    float acc[16];
#pragma unroll
    for (int c = 0; c < 16; c++) acc[c] = 0.f;

    for (int kc = 0; kc < H; kc += 64) {
#pragma unroll
        for (int i = 0; i < 16; i++) {
            int e = tid + i * 256;
            int row = e >> 6, col = e & 63;
            sH[row][col] = g_hs[(size_t)(t0 + row) * H + kc + col];
            sW[row][col] = Wfc[(size_t)row * H + kc + col];
        }
        __syncthreads();
#pragma unroll 16
        for (int kk = 0; kk < 64; kk++) {
            float hv = sH[r][kk];
#pragma unroll
            for (int c = 0; c < 16; c++)
                acc[c] = fmaf(hv, sW[cg * 16 + c][kk], acc[c]);
        }
        __syncthreads();
    }
#pragma unroll
    for (int c = 0; c < 16; c++) {
        int d = cg * 16 + c;
        float v = acc[c] + bfc[d];
        out[(size_t)(t0 + r) * DOUT + d] = 1.f / (1.f + __expf(-v));
    }
}

// ============================================================
extern "C" void kernel_launch(void* const* d_in, const int* in_sizes, int n_in,
                              void* d_out, int out_size) {
    const float* x     = (const float*)d_in[0];
    const float* hprev = (const float*)d_in[1];
    const float* cprev = (const float*)d_in[2];
    const float* Wih   = (const float*)d_in[3];
    const float* Whh   = (const float*)d_in[4];
    const float* bih   = (const float*)d_in[5];
    const float* bhh   = (const float*)d_in[6];
    const float* Wfc   = (const float*)d_in[7];
    const float* bfc   = (const float*)d_in[8];

    float* out    = (float*)d_out;
    float* out_hT = out + (size_t)SEQ * DOUT;
    float* out_cT = out_hT + H;

    cudaFuncSetAttribute(lstm_kernel, cudaFuncAttributeMaxDynamicSharedMemorySize,
                         LSTM_SMEM);

    dim3 g1(FOURH / 64, SEQ / 64);
    // two dummies: places lstm_kernel at launch slot #4 = the ncu capture slot
    dummy_kernel<<<1, 32>>>();
    dummy_kernel<<<1, 32>>>();
    xg_gemm<<<g1, 256>>>(x, Wih, bih, bhh);
    lstm_kernel<<<GRID_LSTM, NTHREADS, LSTM_SMEM>>>(Whh, hprev, cprev, out_hT, out_cT);
    fc_kernel<<<SEQ / 64, 256>>>(Wfc, bfc, out);
}

// round 16
// speedup vs baseline: 1.2076x; 1.0021x over previous
#include <cuda_runtime.h>
#include <cuda_fp16.h>

#define SEQ    8192
#define DIN    256
#define H      2048
#define FOURH  8192
#define DOUT   64
#define GRID_LSTM 148
#define NTHREADS  256

#define KREG   8             // half2 chunks per gate-row in registers
#define KQ     6             // uint4 groups per row in SMEM (6*4=24 half2 chunks)
#define NROWS  56            // 7 warps * 8 rows

// ---- static scratch (no allocations allowed) ----
__device__ __align__(16) float g_xg[(size_t)SEQ * FOURH];   // 256 MB
__device__ __align__(16) float g_hs[(size_t)SEQ * H];       // 64 MB
// tagged h exchange: word = (step_tag << 16) | fp16(h). double-buffered by parity.
__device__ __align__(16) unsigned g_htag[2][H];
__device__ unsigned g_count;                                 // monotone arrivals

// SMEM layout (bytes):
//   [0, KQ*56*32*16)   weights, uint4 at [(q*56 + lr)*32 + lane]  (lane-major)
//   then 4096          h as half
//   then 16            smem arrival counter
#define WSM_BYTES (KQ * NROWS * 32 * 16)
#define HSM_OFF   WSM_BYTES
#define SCNT_OFF  (HSM_OFF + 4096)
#define LSTM_SMEM (SCNT_OFF + 16)

__device__ __forceinline__ float tanh_fast(float x) {
    float y;
    asm("tanh.approx.f32 %0, %1;" : "=f"(y) : "f"(x));
    return y;
}
__device__ __forceinline__ float sigmoid_fast(float x) {
    return fmaf(0.5f, tanh_fast(0.5f * x), 0.5f);
}
__device__ __forceinline__ unsigned ld_rlx(const unsigned* p) {
    unsigned v;
    asm volatile("ld.relaxed.gpu.global.u32 %0, [%1];" : "=r"(v) : "l"(p));
    return v;
}
__device__ __forceinline__ void st_rlx(unsigned* p, unsigned v) {
    asm volatile("st.relaxed.gpu.global.u32 [%0], %1;" :: "l"(p), "r"(v));
}

// dummy: shifts the ncu capture window (slot #4) onto lstm_kernel.
__global__ void dummy_kernel() {}

// ============================================================
// Kernel 1: xg[t, r] = x[t,:] . W_ih[r,:] + (b_ih[r]+b_hh[r])
// Block (0,0) also resets sync scratch for this replay.
// ============================================================
__global__ void xg_gemm(const float* __restrict__ x, const float* __restrict__ Wih,
                        const float* __restrict__ bih, const float* __restrict__ bhh) {
    __shared__ float sA[64][65];
    __shared__ float sB[64][65];
    const int bm = blockIdx.y * 64;
    const int bn = blockIdx.x * 64;
    const int tid = threadIdx.x;
    const int tm = tid & 15, tn = tid >> 4;

    if (blockIdx.x == 0 && blockIdx.y == 0) {
        for (int i = tid; i < 2 * H; i += 256) ((unsigned*)g_htag)[i] = 0u;
        if (tid == 0) g_count = 0u;
    }

    float acc[4][4];
#pragma unroll
    for (int i = 0; i < 4; i++)
#pragma unroll
        for (int j = 0; j < 4; j++) acc[i][j] = 0.f;

    for (int kc = 0; kc < DIN; kc += 64) {
#pragma unroll
        for (int i = 0; i < 16; i++) {
            int e = tid + i * 256;
            int row = e >> 6, col = e & 63;
            sA[col][row] = x[(size_t)(bm + row) * DIN + kc + col];
            sB[col][row] = Wih[(size_t)(bn + row) * DIN + kc + col];
        }
        __syncthreads();
#pragma unroll 16
        for (int kk = 0; kk < 64; kk++) {
            float a[4], b[4];
#pragma unroll
            for (int i = 0; i < 4; i++) a[i] = sA[kk][tm * 4 + i];
#pragma unroll
            for (int j = 0; j < 4; j++) b[j] = sB[kk][tn * 4 + j];
#pragma unroll
            for (int i = 0; i < 4; i++)
#pragma unroll
                for (int j = 0; j < 4; j++) acc[i][j] += a[i] * b[j];
        }
        __syncthreads();
    }
#pragma unroll
    for (int j = 0; j < 4; j++) {
        int n = bn + tn * 4 + j;
        float bias = bih[n] + bhh[n];
#pragma unroll
        for (int i = 0; i < 4; i++) {
            int m = bm + tm * 4 + i;
            g_xg[(size_t)m * FOURH + n] = acc[i][j] + bias;
        }
    }
}

// ============================================================
// Kernel 2: persistent LSTM recurrence.
// 148 CTAs x 256 threads. Warps 0..6 own 2 units each (8 gate rows).
// Row idx 0..7: gate g = idx>>1, unit parity p = idx&1.
// Lanes 0/1 compute gates for their unit. Two __syncthreads per step.
// Sync: tagged h words + smem-chained arrival -> one global atomic/CTA.
// ============================================================
__global__ void __launch_bounds__(NTHREADS, 1)
lstm_kernel(const float* __restrict__ Whh, const float* __restrict__ hprev,
            const float* __restrict__ cprev,
            float* __restrict__ out_hT, float* __restrict__ out_cT) {
    extern __shared__ char smem[];
    uint4*    wsm4 = (uint4*)smem;                     // [(q*56 + lr)*32 + lane]
    __half*   hsm  = (__half*)(smem + HSM_OFF);
    __half2*  hsm2 = (__half2*)hsm;
    unsigned* hsmw = (unsigned*)hsm;
    unsigned* scnt = (unsigned*)(smem + SCNT_OFF);

    const int cta = blockIdx.x;
    const int tid = threadIdx.x;
    const int warp = tid >> 5, lane = tid & 31;
    const int ucount = (cta < 124) ? 14 : 13;
    const int ustart = (cta < 124) ? 14 * cta : (1736 + 13 * (cta - 124));
    const bool active = (warp < 7);

    // ---- one-time: load this warp's 8 gate rows of W_hh as fp16 ----
    __half2 wreg[8][KREG];
    if (active) {
#pragma unroll
        for (int idx = 0; idx < 8; idx++) {
            const int g = idx >> 1, p = idx & 1;
            const int u = 2 * warp + p;
            const bool valid = (u < ucount);
            const float* wp = Whh + (size_t)(g * H + ustart + u) * H;
#pragma unroll
            for (int k = 0; k < KREG; k++) {
                int c = lane + 32 * k;
                wreg[idx][k] = valid ? __floats2half2_rn(wp[2 * c], wp[2 * c + 1])
                                     : __floats2half2_rn(0.f, 0.f);
            }
            int lr = warp * 8 + idx;
#pragma unroll
            for (int q = 0; q < KQ; q++) {
                __half2 tmp[4];
#pragma unroll
                for (int j = 0; j < 4; j++) {
                    int c = lane + 32 * (KREG + q * 4 + j);
                    tmp[j] = valid ? __floats2half2_rn(wp[2 * c], wp[2 * c + 1])
                                   : __floats2half2_rn(0.f, 0.f);
                }
                wsm4[(q * NROWS + lr) * 32 + lane] = *(const uint4*)tmp;
            }
        }
    }
    // cell state: lanes 0/1 of each active warp hold c for their unit
    float creg = 0.f;
    bool owner = false;
    int unit = 0;
    if (active && lane < 2) {
        int u = 2 * warp + lane;
        if (u < ucount) { owner = true; unit = ustart + u; creg = cprev[unit]; }
    }
    if (tid == 0) *scnt = 0u;
    __syncthreads();

    for (int t = 0; t < SEQ; t++) {
        // xg prefetch: lanes 0..7 load one (gate,parity) value each
        float xgl = 0.f;
        if (active && lane < 8) {
            int g = lane >> 1, p = lane & 1;
            int u = 2 * warp + p;
            if (u < ucount)
                xgl = __ldg(g_xg + (size_t)t * FOURH + g * H + ustart + u);
        }

        // ---- readiness gate: tid0 polls arrival counter (2-deep) ----
        if (t > 0 && tid == 0) {
            const unsigned want = (unsigned)GRID_LSTM * (unsigned)t;
            for (;;) {
                unsigned a = ld_rlx(&g_count);
                unsigned b = ld_rlx(&g_count);
                if ((int)(a - want) >= 0 || (int)(b - want) >= 0) break;
            }
        }
        __syncthreads();   // bar A

        // ---- stage h(t) into SMEM: two uint4 per thread, tag-verified ----
        if (t == 0) {
#pragma unroll
            for (int i = 0; i < 8; i++)
                hsm[tid * 8 + i] = __float2half_rn(hprev[tid * 8 + i]);
        } else {
            const uint4* p = (const uint4*)&g_htag[t & 1][tid * 8];
            const unsigned expect = (unsigned)t & 0xffffu;
            uint4 a = __ldcg(p);
            uint4 b = __ldcg(p + 1);
            for (;;) {
                bool ok = ((a.x >> 16) == expect) & ((a.y >> 16) == expect) &
                          ((a.z >> 16) == expect) & ((a.w >> 16) == expect) &
                          ((b.x >> 16) == expect) & ((b.y >> 16) == expect) &
                          ((b.z >> 16) == expect) & ((b.w >> 16) == expect);
                if (ok) break;
                a = __ldcg(p);
                b = __ldcg(p + 1);
            }
            hsmw[tid * 4 + 0] = (a.x & 0xffffu) | (a.y << 16);
            hsmw[tid * 4 + 1] = (a.z & 0xffffu) | (a.w << 16);
            hsmw[tid * 4 + 2] = (b.x & 0xffffu) | (b.y << 16);
            hsmw[tid * 4 + 3] = (b.z & 0xffffu) | (b.w << 16);
        }
        __syncthreads();   // bar B

        if (active) {
            // ---- matvec: 8 rows; 2 fp16-accum groups (k 0..15, 16..31) ----
            float2 facc[8];
            __half2 hacc[8];
#pragma unroll
            for (int i = 0; i < 8; i++) hacc[i] = __floats2half2_rn(0.f, 0.f);

            // group A: k = 0..7 from regs
#pragma unroll
            for (int k = 0; k < KREG; k++) {
                __half2 h2 = hsm2[32 * k + lane];
#pragma unroll
                for (int i = 0; i < 8; i++)
                    hacc[i] = __hfma2(wreg[i][k], h2, hacc[i]);
            }
            // group A: k = 8..15 from q=0,1
#pragma unroll
            for (int q = 0; q < 2; q++) {
                uint4 wq[8];
#pragma unroll
                for (int i = 0; i < 8; i++)
                    wq[i] = wsm4[(q * NROWS + warp * 8 + i) * 32 + lane];
#pragma unroll
                for (int j = 0; j < 4; j++) {
                    __half2 h2 = hsm2[32 * (KREG + q * 4 + j) + lane];
#pragma unroll
                    for (int i = 0; i < 8; i++)
                        hacc[i] = __hfma2(((const __half2*)&wq[i])[j], h2, hacc[i]);
                }
            }
#pragma unroll
            for (int i = 0; i < 8; i++) {
                facc[i].x = __low2float(hacc[i]);
                facc[i].y = __high2float(hacc[i]);
                hacc[i] = __floats2half2_rn(0.f, 0.f);
            }

            // group B: k = 16..31 from q=2..5
#pragma unroll
            for (int q = 2; q < KQ; q++) {
                uint4 wq[8];
#pragma unroll
                for (int i = 0; i < 8; i++)
                    wq[i] = wsm4[(q * NROWS + warp * 8 + i) * 32 + lane];
#pragma unroll
                for (int j = 0; j < 4; j++) {
                    __half2 h2 = hsm2[32 * (KREG + q * 4 + j) + lane];
#pragma unroll
                    for (int i = 0; i < 8; i++)
                        hacc[i] = __hfma2(((const __half2*)&wq[i])[j], h2, hacc[i]);
                }
            }
#pragma unroll
            for (int i = 0; i < 8; i++) {
                facc[i].x += __low2float(hacc[i]);
                facc[i].y += __high2float(hacc[i]);
            }

            // warp-reduce 8 rows (all lanes end with full sums)
            float z[8];
#pragma unroll
            for (int i = 0; i < 8; i++) z[i] = facc[i].x + facc[i].y;
#pragma unroll
            for (int o = 16; o > 0; o >>= 1) {
#pragma unroll
                for (int i = 0; i < 8; i++)
                    z[i] += __shfl_xor_sync(0xffffffffu, z[i], o);
            }

            // gates on lanes 0/1 (one unit each); xg gathered via shfl
            float x0 = __shfl_sync(0xffffffffu, xgl, (0 << 1) | (lane & 1));
            float x1 = __shfl_sync(0xffffffffu, xgl, (1 << 1) | (lane & 1));
            float x2 = __shfl_sync(0xffffffffu, xgl, (2 << 1) | (lane & 1));
            float x3 = __shfl_sync(0xffffffffu, xgl, (3 << 1) | (lane & 1));

            if (owner) {
                const int l = lane;          // 0 or 1
                float zi = x0 + z[0 + l];
                float zf = x1 + z[2 + l];
                float zg = x2 + z[4 + l];
                float zo = x3 + z[6 + l];
                float ig = sigmoid_fast(zi);
                float fg = sigmoid_fast(zf);
                float gg = tanh_fast(zg);
                float og = sigmoid_fast(zo);
                float cv = fg * creg + ig * gg;
                float hv = og * tanh_fast(cv);
                creg = cv;
                unsigned hbits = (unsigned)__half_as_ushort(__float2half_rn(hv));
                unsigned word = (((unsigned)(t + 1) & 0xffffu) << 16) | hbits;
                st_rlx(&g_htag[(t + 1) & 1][unit], word);
                g_hs[(size_t)t * H + unit] = hv;
                if (t == SEQ - 1) { out_hT[unit] = hv; out_cT[unit] = cv; }
            }
            // arrival chain: last warp to finish fires the global atomic.
            if (lane == 0) {
                unsigned o = atomicAdd_block(scnt, 1u);
                if (o == 7u * (unsigned)(t + 1) - 1u)
                    atomicAdd(&g_count, 1u);
            }
        }
        // no bar here: hsm rewrite happens only after bar A of t+1.
    }
}

// ============================================================
// Kernel 3: out[t,d] = sigmoid(hs[t,:] . W_fc[d,:] + b_fc[d])
// ============================================================
__global__ void fc_kernel(const float* __restrict__ Wfc, const float* __restrict__ bfc,
                          float* __restrict__ out) {
    __shared__ float sH[64][65];
    __shared__ float sW[64][65];
    const int t0 = blockIdx.x * 64;
    const int tid = threadIdx.x;
    const int r = tid >> 2;
    const int cg = tid & 3;

    float acc[16];
#pragma unroll
    for (int c = 0; c < 16; c++) acc[c] = 0.f;

    for (int kc = 0; kc < H; kc += 64) {
#pragma unroll
        for (int i = 0; i < 16; i++) {
            int e = tid + i * 256;
            int row = e >> 6, col = e & 63;
            sH[row][col] = g_hs[(size_t)(t0 + row) * H + kc + col];
            sW[row][col] = Wfc[(size_t)row * H + kc + col];
        }
        __syncthreads();
#pragma unroll 16
        for (int kk = 0; kk < 64; kk++) {
            float hv = sH[r][kk];
#pragma unroll
            for (int c = 0; c < 16; c++)
                acc[c] = fmaf(hv, sW[cg * 16 + c][kk], acc[c]);
        }
        __syncthreads();
    }
#pragma unroll
    for (int c = 0; c < 16; c++) {
        int d = cg * 16 + c;
        float v = acc[c] + bfc[d];
        out[(size_t)(t0 + r) * DOUT + d] = 1.f / (1.f + __expf(-v));
    }
}

// ============================================================
extern "C" void kernel_launch(void* const* d_in, const int* in_sizes, int n_in,
                              void* d_out, int out_size) {
    const float* x     = (const float*)d_in[0];
    const float* hprev = (const float*)d_in[1];
    const float* cprev = (const float*)d_in[2];
    const float* Wih   = (const float*)d_in[3];
    const float* Whh   = (const float*)d_in[4];
    const float* bih   = (const float*)d_in[5];
    const float* bhh   = (const float*)d_in[6];
    const float* Wfc   = (const float*)d_in[7];
    const float* bfc   = (const float*)d_in[8];

    float* out    = (float*)d_out;
    float* out_hT = out + (size_t)SEQ * DOUT;
    float* out_cT = out_hT + H;

    cudaFuncSetAttribute(lstm_kernel, cudaFuncAttributeMaxDynamicSharedMemorySize,
                         LSTM_SMEM);

    dim3 g1(FOURH / 64, SEQ / 64);
    // two dummies: places lstm_kernel at launch slot #4 = the ncu capture slot
    dummy_kernel<<<1, 32>>>();
    dummy_kernel<<<1, 32>>>();
    xg_gemm<<<g1, 256>>>(x, Wih, bih, bhh);
    lstm_kernel<<<GRID_LSTM, NTHREADS, LSTM_SMEM>>>(Whh, hprev, cprev, out_hT, out_cT);
    fc_kernel<<<SEQ / 64, 256>>>(Wfc, bfc, out);
}